// round 1
// baseline (speedup 1.0000x reference)
#include <cuda_runtime.h>
#include <math.h>

// Problem constants
#define BB   4
#define SS   2048
#define DD   1024
#define HH   16
#define DKK  64
#define DFFq 4096
#define ROWS (BB*SS)          // 8192

// ---------------------------------------------------------------------------
// Scratch (device globals; no allocation allowed)
// ---------------------------------------------------------------------------
__device__ float g_q  [ (size_t)ROWS*DD ];
__device__ float g_k  [ (size_t)ROWS*DD ];
__device__ float g_v  [ (size_t)ROWS*DD ];
__device__ float g_ctx[ (size_t)ROWS*DD ];
__device__ float g_t0 [ (size_t)ROWS*DD ];   // residual-summed pre-LN buffer (reused)
__device__ float g_x1 [ (size_t)ROWS*DD ];   // post-LN1
__device__ float g_hb [ (size_t)ROWS*DFFq ]; // FFN hidden

// ---------------------------------------------------------------------------
// GEMM: C[M,N] = A[M,K] * Bw[N,K]^T + bias[N] (+ Res) (+ relu)
// 128x128 tile, BK=8, 256 threads, 8x8 per-thread accumulators
// ---------------------------------------------------------------------------
template<int RELU, int RES>
__global__ void __launch_bounds__(256, 2)
gemm_nt(const float* __restrict__ A, const float* __restrict__ Bw,
        const float* __restrict__ bias, const float* __restrict__ Res,
        float* __restrict__ C, int M, int N, int K)
{
    __shared__ __align__(16) float As[8][132];
    __shared__ __align__(16) float Bs[8][132];

    const int bm = blockIdx.y, bn = blockIdx.x;
    const int t  = threadIdx.x;
    const int tx = t & 15, ty = t >> 4;

    const int lrow = t >> 1;         // 0..127
    const int lkg  = (t & 1) * 4;    // 0 or 4

    const float* Aptr = A  + (size_t)(bm*128 + lrow) * K + lkg;
    const float* Bptr = Bw + (size_t)(bn*128 + lrow) * K + lkg;

    float acc[8][8];
#pragma unroll
    for (int i = 0; i < 8; i++)
#pragma unroll
        for (int j = 0; j < 8; j++) acc[i][j] = 0.f;

    for (int k0 = 0; k0 < K; k0 += 8) {
        float4 av = *(const float4*)(Aptr + k0);
        float4 bv = *(const float4*)(Bptr + k0);
        As[lkg+0][lrow] = av.x; As[lkg+1][lrow] = av.y;
        As[lkg+2][lrow] = av.z; As[lkg+3][lrow] = av.w;
        Bs[lkg+0][lrow] = bv.x; Bs[lkg+1][lrow] = bv.y;
        Bs[lkg+2][lrow] = bv.z; Bs[lkg+3][lrow] = bv.w;
        __syncthreads();

#pragma unroll
        for (int kk = 0; kk < 8; kk++) {
            float a[8], b[8];
            float4 t0 = *(const float4*)&As[kk][ty*8];
            float4 t1 = *(const float4*)&As[kk][ty*8+4];
            float4 u0 = *(const float4*)&Bs[kk][tx*8];
            float4 u1 = *(const float4*)&Bs[kk][tx*8+4];
            a[0]=t0.x; a[1]=t0.y; a[2]=t0.z; a[3]=t0.w;
            a[4]=t1.x; a[5]=t1.y; a[6]=t1.z; a[7]=t1.w;
            b[0]=u0.x; b[1]=u0.y; b[2]=u0.z; b[3]=u0.w;
            b[4]=u1.x; b[5]=u1.y; b[6]=u1.z; b[7]=u1.w;
#pragma unroll
            for (int i = 0; i < 8; i++)
#pragma unroll
                for (int j = 0; j < 8; j++)
                    acc[i][j] = fmaf(a[i], b[j], acc[i][j]);
        }
        __syncthreads();
    }

    // epilogue (M,N multiples of 128 — no bounds checks)
#pragma unroll
    for (int i = 0; i < 8; i++) {
        const int row = bm*128 + ty*8 + i;
#pragma unroll
        for (int j = 0; j < 8; j += 4) {
            const int col = bn*128 + tx*8 + j;
            float4 r;
            r.x = acc[i][j+0] + bias[col+0];
            r.y = acc[i][j+1] + bias[col+1];
            r.z = acc[i][j+2] + bias[col+2];
            r.w = acc[i][j+3] + bias[col+3];
            if (RES) {
                float4 rv = *(const float4*)&Res[(size_t)row*N + col];
                r.x += rv.x; r.y += rv.y; r.z += rv.z; r.w += rv.w;
            }
            if (RELU) {
                r.x = fmaxf(r.x, 0.f); r.y = fmaxf(r.y, 0.f);
                r.z = fmaxf(r.z, 0.f); r.w = fmaxf(r.w, 0.f);
            }
            *(float4*)&C[(size_t)row*N + col] = r;
        }
    }
}

// ---------------------------------------------------------------------------
// Flash attention: 64-query block per CTA, 64-key tiles, fp32 online softmax
// grid: (S/64, B*H), 256 threads. Layout: q/k/v/ctx are [B,S,D] with head h
// occupying columns h*64..h*64+63.
// ---------------------------------------------------------------------------
__global__ void __launch_bounds__(256)
attn_kernel(const float* __restrict__ Q, const float* __restrict__ Kf,
            const float* __restrict__ Vf, const int* __restrict__ mask,
            float* __restrict__ ctx)
{
    extern __shared__ float sm[];
    float* Qs  = sm;                 // [64][65]
    float* Kst = Qs  + 64*65;        // [64][64]  (d-major: Kst[d*64+c])
    float* Vs  = Kst + 64*64;        // [64][64]  (Vs[c*64+d])
    float* Ps  = Vs  + 64*64;        // [64][65]
    int*   msk = (int*)(Ps + 64*65); // [64]

    const int qb = blockIdx.x, bh = blockIdx.y;
    const int b = bh / HH, h = bh % HH;
    const int t = threadIdx.x, tx = t & 15, ty = t >> 4;

    const size_t base = (size_t)b * SS * DD + (size_t)h * DKK;

    // load + prescale Q tile (scale = 1/sqrt(64) = 0.125)
    {
        const int r = t >> 2, d0 = (t & 3) * 16;
        const float* qp = Q + base + (size_t)(qb*64 + r) * DD + d0;
#pragma unroll
        for (int i = 0; i < 16; i += 4) {
            float4 v = *(const float4*)(qp + i);
            Qs[r*65 + d0 + i + 0] = v.x * 0.125f;
            Qs[r*65 + d0 + i + 1] = v.y * 0.125f;
            Qs[r*65 + d0 + i + 2] = v.z * 0.125f;
            Qs[r*65 + d0 + i + 3] = v.w * 0.125f;
        }
    }

    float m[4], l[4], o[4][4];
#pragma unroll
    for (int i = 0; i < 4; i++) {
        m[i] = -1e30f; l[i] = 0.f;
#pragma unroll
        for (int j = 0; j < 4; j++) o[i][j] = 0.f;
    }

    for (int kc = 0; kc < SS; kc += 64) {
        __syncthreads();  // previous PV done before overwriting Kst/Vs/msk
        {
            const int c = t >> 2, d0 = (t & 3) * 16;
            const float* kp = Kf + base + (size_t)(kc + c) * DD + d0;
            const float* vp = Vf + base + (size_t)(kc + c) * DD + d0;
#pragma unroll
            for (int i = 0; i < 16; i += 4) {
                float4 kv = *(const float4*)(kp + i);
                Kst[(d0+i+0)*64 + c] = kv.x;
                Kst[(d0+i+1)*64 + c] = kv.y;
                Kst[(d0+i+2)*64 + c] = kv.z;
                Kst[(d0+i+3)*64 + c] = kv.w;
                float4 vv = *(const float4*)(vp + i);
                *(float4*)&Vs[c*64 + d0 + i] = vv;
            }
            if (t < 64) msk[t] = mask[(size_t)b * SS + kc + t];
        }
        __syncthreads();

        // scores s[4 rows][4 cols]
        float s[4][4];
#pragma unroll
        for (int i = 0; i < 4; i++)
#pragma unroll
            for (int j = 0; j < 4; j++) s[i][j] = 0.f;

        for (int d = 0; d < 64; d++) {
            float a0 = Qs[(ty*4+0)*65 + d];
            float a1 = Qs[(ty*4+1)*65 + d];
            float a2 = Qs[(ty*4+2)*65 + d];
            float a3 = Qs[(ty*4+3)*65 + d];
            float4 bb = *(const float4*)&Kst[d*64 + tx*4];
            s[0][0] = fmaf(a0, bb.x, s[0][0]); s[0][1] = fmaf(a0, bb.y, s[0][1]);
            s[0][2] = fmaf(a0, bb.z, s[0][2]); s[0][3] = fmaf(a0, bb.w, s[0][3]);
            s[1][0] = fmaf(a1, bb.x, s[1][0]); s[1][1] = fmaf(a1, bb.y, s[1][1]);
            s[1][2] = fmaf(a1, bb.z, s[1][2]); s[1][3] = fmaf(a1, bb.w, s[1][3]);
            s[2][0] = fmaf(a2, bb.x, s[2][0]); s[2][1] = fmaf(a2, bb.y, s[2][1]);
            s[2][2] = fmaf(a2, bb.z, s[2][2]); s[2][3] = fmaf(a2, bb.w, s[2][3]);
            s[3][0] = fmaf(a3, bb.x, s[3][0]); s[3][1] = fmaf(a3, bb.y, s[3][1]);
            s[3][2] = fmaf(a3, bb.z, s[3][2]); s[3][3] = fmaf(a3, bb.w, s[3][3]);
        }

#pragma unroll
        for (int j = 0; j < 4; j++)
            if (msk[tx*4 + j] == 0) {
#pragma unroll
                for (int i = 0; i < 4; i++) s[i][j] = -1e9f;
            }

        // online softmax per row
#pragma unroll
        for (int i = 0; i < 4; i++) {
            float mt = fmaxf(fmaxf(s[i][0], s[i][1]), fmaxf(s[i][2], s[i][3]));
#pragma unroll
            for (int off = 1; off < 16; off <<= 1)
                mt = fmaxf(mt, __shfl_xor_sync(0xffffffffu, mt, off));
            float mn = fmaxf(m[i], mt);
            float alpha = __expf(m[i] - mn);
            m[i] = mn;
            float psum = 0.f;
#pragma unroll
            for (int j = 0; j < 4; j++) {
                float p = __expf(s[i][j] - mn);
                s[i][j] = p; psum += p;
            }
#pragma unroll
            for (int off = 1; off < 16; off <<= 1)
                psum += __shfl_xor_sync(0xffffffffu, psum, off);
            l[i] = l[i] * alpha + psum;
#pragma unroll
            for (int j = 0; j < 4; j++) o[i][j] *= alpha;
#pragma unroll
            for (int j = 0; j < 4; j++)
                Ps[(ty*4+i)*65 + tx*4 + j] = s[i][j];
        }
        __syncthreads();

        // o += P @ V  (thread owns rows ty*4.., dims tx*4..)
        for (int c = 0; c < 64; c++) {
            float a0 = Ps[(ty*4+0)*65 + c];
            float a1 = Ps[(ty*4+1)*65 + c];
            float a2 = Ps[(ty*4+2)*65 + c];
            float a3 = Ps[(ty*4+3)*65 + c];
            float4 bb = *(const float4*)&Vs[c*64 + tx*4];
            o[0][0] = fmaf(a0, bb.x, o[0][0]); o[0][1] = fmaf(a0, bb.y, o[0][1]);
            o[0][2] = fmaf(a0, bb.z, o[0][2]); o[0][3] = fmaf(a0, bb.w, o[0][3]);
            o[1][0] = fmaf(a1, bb.x, o[1][0]); o[1][1] = fmaf(a1, bb.y, o[1][1]);
            o[1][2] = fmaf(a1, bb.z, o[1][2]); o[1][3] = fmaf(a1, bb.w, o[1][3]);
            o[2][0] = fmaf(a2, bb.x, o[2][0]); o[2][1] = fmaf(a2, bb.y, o[2][1]);
            o[2][2] = fmaf(a2, bb.z, o[2][2]); o[2][3] = fmaf(a2, bb.w, o[2][3]);
            o[3][0] = fmaf(a3, bb.x, o[3][0]); o[3][1] = fmaf(a3, bb.y, o[3][1]);
            o[3][2] = fmaf(a3, bb.z, o[3][2]); o[3][3] = fmaf(a3, bb.w, o[3][3]);
        }
    }

#pragma unroll
    for (int i = 0; i < 4; i++) {
        float inv = 1.0f / l[i];
        float4 r;
        r.x = o[i][0]*inv; r.y = o[i][1]*inv; r.z = o[i][2]*inv; r.w = o[i][3]*inv;
        *(float4*)&ctx[base + (size_t)(qb*64 + ty*4 + i) * DD + tx*4] = r;
    }
}

// ---------------------------------------------------------------------------
// LayerNorm: torch-style, unbiased std (ddof=1), eps added to std.
// One row per CTA, 256 threads, 4 elems/thread (D=1024).
// ---------------------------------------------------------------------------
__global__ void __launch_bounds__(256)
ln_kernel(const float* __restrict__ in, const float* __restrict__ g,
          const float* __restrict__ be, float* __restrict__ out)
{
    __shared__ float red1[8];
    __shared__ float red2[8];
    const int row = blockIdx.x;
    const int t = threadIdx.x;
    const int warp = t >> 5, lane = t & 31;

    float4 v = *(const float4*)(in + (size_t)row * DD + t*4);

    float s = v.x + v.y + v.z + v.w;
#pragma unroll
    for (int off = 16; off; off >>= 1) s += __shfl_xor_sync(0xffffffffu, s, off);
    if (lane == 0) red1[warp] = s;
    __syncthreads();
    float tot = 0.f;
#pragma unroll
    for (int i = 0; i < 8; i++) tot += red1[i];
    const float mean = tot * (1.0f / DD);

    float dx = v.x - mean, dy = v.y - mean, dz = v.z - mean, dw = v.w - mean;
    float sq = dx*dx + dy*dy + dz*dz + dw*dw;
#pragma unroll
    for (int off = 16; off; off >>= 1) sq += __shfl_xor_sync(0xffffffffu, sq, off);
    if (lane == 0) red2[warp] = sq;
    __syncthreads();
    float sqtot = 0.f;
#pragma unroll
    for (int i = 0; i < 8; i++) sqtot += red2[i];

    const float var = sqtot * (1.0f / (DD - 1));
    const float inv = 1.0f / (sqrtf(var) + 1e-6f);

    float4 gv = *(const float4*)(g  + t*4);
    float4 bv = *(const float4*)(be + t*4);
    float4 r;
    r.x = dx * inv * gv.x + bv.x;
    r.y = dy * inv * gv.y + bv.y;
    r.z = dz * inv * gv.z + bv.z;
    r.w = dw * inv * gv.w + bv.w;
    *(float4*)(out + (size_t)row * DD + t*4) = r;
}

// ---------------------------------------------------------------------------
// kernel_launch
// ---------------------------------------------------------------------------
extern "C" void kernel_launch(void* const* d_in, const int* in_sizes, int n_in,
                              void* d_out, int out_size)
{
    const float* x    = (const float*)d_in[0];
    const int*   mask = (const int*)  d_in[1];
    const float* Wq = (const float*)d_in[2];  const float* bq = (const float*)d_in[3];
    const float* Wk = (const float*)d_in[4];  const float* bk = (const float*)d_in[5];
    const float* Wv = (const float*)d_in[6];  const float* bv = (const float*)d_in[7];
    const float* Wo = (const float*)d_in[8];  const float* bo = (const float*)d_in[9];
    const float* W1 = (const float*)d_in[10]; const float* b1 = (const float*)d_in[11];
    const float* W2 = (const float*)d_in[12]; const float* b2 = (const float*)d_in[13];
    const float* g1 = (const float*)d_in[14]; const float* be1 = (const float*)d_in[15];
    const float* g2 = (const float*)d_in[16]; const float* be2 = (const float*)d_in[17];
    float* out = (float*)d_out;

    float *pq, *pk, *pv, *pctx, *pt0, *px1, *ph;
    cudaGetSymbolAddress((void**)&pq,   g_q);
    cudaGetSymbolAddress((void**)&pk,   g_k);
    cudaGetSymbolAddress((void**)&pv,   g_v);
    cudaGetSymbolAddress((void**)&pctx, g_ctx);
    cudaGetSymbolAddress((void**)&pt0,  g_t0);
    cudaGetSymbolAddress((void**)&px1,  g_x1);
    cudaGetSymbolAddress((void**)&ph,   g_hb);

    const int attn_smem = (64*65 + 64*64 + 64*64 + 64*65) * 4 + 64 * 4;
    cudaFuncSetAttribute(attn_kernel, cudaFuncAttributeMaxDynamicSharedMemorySize,
                         attn_smem);

    dim3 blk(256);
    dim3 gD(DD/128,   ROWS/128);   // N=1024
    dim3 gF(DFFq/128, ROWS/128);   // N=4096

    // QKV projections
    gemm_nt<0,0><<<gD, blk>>>(x, Wq, bq, nullptr, pq, ROWS, DD, DD);
    gemm_nt<0,0><<<gD, blk>>>(x, Wk, bk, nullptr, pk, ROWS, DD, DD);
    gemm_nt<0,0><<<gD, blk>>>(x, Wv, bv, nullptr, pv, ROWS, DD, DD);

    // attention
    attn_kernel<<<dim3(SS/64, BB*HH), blk, attn_smem>>>(pq, pk, pv, mask, pctx);

    // output projection + residual, then LN1
    gemm_nt<0,1><<<gD, blk>>>(pctx, Wo, bo, x, pt0, ROWS, DD, DD);
    ln_kernel<<<ROWS, blk>>>(pt0, g1, be1, px1);

    // FFN
    gemm_nt<1,0><<<gF, blk>>>(px1, W1, b1, nullptr, ph, ROWS, DFFq, DD);
    gemm_nt<0,1><<<gD, blk>>>(ph, W2, b2, px1, pt0, ROWS, DD, DFFq);

    // LN2 -> output
    ln_kernel<<<ROWS, blk>>>(pt0, g2, be2, out);
}

// round 3
// speedup vs baseline: 1.9852x; 1.9852x over previous
#include <cuda_runtime.h>
#include <math.h>

// Problem constants
#define BB   4
#define SS   2048
#define DD   1024
#define HH   16
#define DKK  64
#define DFFq 4096
#define ROWS (BB*SS)          // 8192

// ---------------------------------------------------------------------------
// Scratch (device globals; no allocation allowed)
// ---------------------------------------------------------------------------
__device__ float g_q  [ (size_t)ROWS*DD ];
__device__ float g_k  [ (size_t)ROWS*DD ];
__device__ float g_v  [ (size_t)ROWS*DD ];
__device__ float g_ctx[ (size_t)ROWS*DD ];
__device__ float g_t0 [ (size_t)ROWS*DD ];
__device__ float g_x1 [ (size_t)ROWS*DD ];
__device__ float g_hb [ (size_t)ROWS*DFFq ];

// ---------------------------------------------------------------------------
// tf32 helpers
// ---------------------------------------------------------------------------
__device__ __forceinline__ unsigned cvt_tf32(float x) {
    unsigned r;
    asm("cvt.rna.tf32.f32 %0, %1;" : "=r"(r) : "f"(x));
    return r;
}

__device__ __forceinline__ void mma_tf32(float* c, const unsigned* a, const unsigned* b) {
    asm volatile(
        "mma.sync.aligned.m16n8k8.row.col.f32.tf32.tf32.f32 "
        "{%0,%1,%2,%3}, {%4,%5,%6,%7}, {%8,%9}, {%0,%1,%2,%3};"
        : "+f"(c[0]), "+f"(c[1]), "+f"(c[2]), "+f"(c[3])
        : "r"(a[0]), "r"(a[1]), "r"(a[2]), "r"(a[3]),
          "r"(b[0]), "r"(b[1]));
}

// ---------------------------------------------------------------------------
// GEMM (tensor-core tf32): C[M,N] = A[M,K] * Bw[N,K]^T + bias (+Res)(+relu)
// CTA tile 128x128, BK=32, 256 threads = 8 warps; warp tile 64x32
// (4x4 m16n8k8 mma tiles). Smem rows padded to 36 words: STS.128 tile
// stores and per-lane fragment LDS are both bank-conflict-free.
// ---------------------------------------------------------------------------
#define SPAD 36

template<int RELU, int RES>
__global__ void __launch_bounds__(256, 2)
gemm_tf32(const float* __restrict__ A, const float* __restrict__ Bw,
          const float* __restrict__ bias, const float* __restrict__ Res,
          float* __restrict__ C, int M, int N, int K)
{
    __shared__ __align__(16) unsigned As[128 * SPAD];
    __shared__ __align__(16) unsigned Bs[128 * SPAD];

    const int t = threadIdx.x;
    const int w = t >> 5, lane = t & 31;
    const int gid = lane >> 2, qid = lane & 3;
    const int bm = blockIdx.y, bn = blockIdx.x;
    const int wm = (w >> 2) * 64;   // warp row offset (0 or 64)
    const int wn = (w & 3) * 32;    // warp col offset (0,32,64,96)

    // Loader mapping: thread handles rows r0+32i, 4 consecutive floats at qc*4
    const int r0 = t >> 3;          // 0..31
    const int qc = t & 7;           // 0..7 (column group of 4 floats)

    const float* Ap = A  + (size_t)(bm*128 + r0) * K + qc*4;
    const float* Bp = Bw + (size_t)(bn*128 + r0) * K + qc*4;

    float pa[16], pb[16];
    // prefetch k-tile 0
#pragma unroll
    for (int i = 0; i < 4; i++) {
        float4 va = *(const float4*)(Ap + (size_t)(32*i) * K);
        float4 vb = *(const float4*)(Bp + (size_t)(32*i) * K);
        pa[i*4+0]=va.x; pa[i*4+1]=va.y; pa[i*4+2]=va.z; pa[i*4+3]=va.w;
        pb[i*4+0]=vb.x; pb[i*4+1]=vb.y; pb[i*4+2]=vb.z; pb[i*4+3]=vb.w;
    }

    float acc[4][4][4];
#pragma unroll
    for (int i = 0; i < 4; i++)
#pragma unroll
        for (int j = 0; j < 4; j++)
#pragma unroll
            for (int c = 0; c < 4; c++) acc[i][j][c] = 0.f;

    for (int k0 = 0; k0 < K; k0 += 32) {
        __syncthreads();   // prev compute done before overwriting smem
        // store prefetched tile to smem (converted to tf32), STS.128
#pragma unroll
        for (int i = 0; i < 4; i++) {
            uint4 sa, sb;
            sa.x = cvt_tf32(pa[i*4+0]); sa.y = cvt_tf32(pa[i*4+1]);
            sa.z = cvt_tf32(pa[i*4+2]); sa.w = cvt_tf32(pa[i*4+3]);
            sb.x = cvt_tf32(pb[i*4+0]); sb.y = cvt_tf32(pb[i*4+1]);
            sb.z = cvt_tf32(pb[i*4+2]); sb.w = cvt_tf32(pb[i*4+3]);
            *(uint4*)&As[(r0 + 32*i) * SPAD + qc*4] = sa;
            *(uint4*)&Bs[(r0 + 32*i) * SPAD + qc*4] = sb;
        }
        __syncthreads();

        // prefetch next k-tile while computing this one
        if (k0 + 32 < K) {
#pragma unroll
            for (int i = 0; i < 4; i++) {
                float4 va = *(const float4*)(Ap + (size_t)(32*i) * K + (k0 + 32));
                float4 vb = *(const float4*)(Bp + (size_t)(32*i) * K + (k0 + 32));
                pa[i*4+0]=va.x; pa[i*4+1]=va.y; pa[i*4+2]=va.z; pa[i*4+3]=va.w;
                pb[i*4+0]=vb.x; pb[i*4+1]=vb.y; pb[i*4+2]=vb.z; pb[i*4+3]=vb.w;
            }
        }

#pragma unroll
        for (int ks = 0; ks < 4; ks++) {
            const int kk = ks * 8;
            unsigned afr[4][4], bfr[4][2];
#pragma unroll
            for (int i = 0; i < 4; i++) {
                const int r = wm + i*16 + gid;
                afr[i][0] = As[r       * SPAD + kk + qid];
                afr[i][1] = As[(r + 8) * SPAD + kk + qid];
                afr[i][2] = As[r       * SPAD + kk + qid + 4];
                afr[i][3] = As[(r + 8) * SPAD + kk + qid + 4];
            }
#pragma unroll
            for (int j = 0; j < 4; j++) {
                const int n = wn + j*8 + gid;
                bfr[j][0] = Bs[n * SPAD + kk + qid];
                bfr[j][1] = Bs[n * SPAD + kk + qid + 4];
            }
#pragma unroll
            for (int i = 0; i < 4; i++)
#pragma unroll
                for (int j = 0; j < 4; j++)
                    mma_tf32(acc[i][j], afr[i], bfr[j]);
        }
    }

    // epilogue: c0,c1 -> (row, col..col+1); c2,c3 -> (row+8, ...)
#pragma unroll
    for (int i = 0; i < 4; i++) {
#pragma unroll
        for (int j = 0; j < 4; j++) {
            const int row = bm*128 + wm + i*16 + gid;
            const int col = bn*128 + wn + j*8 + 2*qid;
            float2 bi = *(const float2*)&bias[col];
            float2 r0v, r1v;
            r0v.x = acc[i][j][0] + bi.x;  r0v.y = acc[i][j][1] + bi.y;
            r1v.x = acc[i][j][2] + bi.x;  r1v.y = acc[i][j][3] + bi.y;
            if (RES) {
                float2 a0 = *(const float2*)&Res[(size_t)row*N + col];
                float2 a1 = *(const float2*)&Res[(size_t)(row+8)*N + col];
                r0v.x += a0.x; r0v.y += a0.y;
                r1v.x += a1.x; r1v.y += a1.y;
            }
            if (RELU) {
                r0v.x = fmaxf(r0v.x, 0.f); r0v.y = fmaxf(r0v.y, 0.f);
                r1v.x = fmaxf(r1v.x, 0.f); r1v.y = fmaxf(r1v.y, 0.f);
            }
            *(float2*)&C[(size_t)row    *N + col] = r0v;
            *(float2*)&C[(size_t)(row+8)*N + col] = r1v;
        }
    }
}

// ---------------------------------------------------------------------------
// Flash attention: 64-query block per CTA, 64-key tiles, fp32 online softmax
// ---------------------------------------------------------------------------
__global__ void __launch_bounds__(256)
attn_kernel(const float* __restrict__ Q, const float* __restrict__ Kf,
            const float* __restrict__ Vf, const int* __restrict__ mask,
            float* __restrict__ ctx)
{
    extern __shared__ float sm[];
    float* Qs  = sm;                 // [64][65]
    float* Kst = Qs  + 64*65;        // [64][64]  (d-major)
    float* Vs  = Kst + 64*64;        // [64][64]
    float* Ps  = Vs  + 64*64;        // [64][65]
    int*   msk = (int*)(Ps + 64*65); // [64]

    const int qb = blockIdx.x, bh = blockIdx.y;
    const int b = bh / HH, h = bh % HH;
    const int t = threadIdx.x, tx = t & 15, ty = t >> 4;

    const size_t base = (size_t)b * SS * DD + (size_t)h * DKK;

    {
        const int r = t >> 2, d0 = (t & 3) * 16;
        const float* qp = Q + base + (size_t)(qb*64 + r) * DD + d0;
#pragma unroll
        for (int i = 0; i < 16; i += 4) {
            float4 v = *(const float4*)(qp + i);
            Qs[r*65 + d0 + i + 0] = v.x * 0.125f;
            Qs[r*65 + d0 + i + 1] = v.y * 0.125f;
            Qs[r*65 + d0 + i + 2] = v.z * 0.125f;
            Qs[r*65 + d0 + i + 3] = v.w * 0.125f;
        }
    }

    float m[4], l[4], o[4][4];
#pragma unroll
    for (int i = 0; i < 4; i++) {
        m[i] = -1e30f; l[i] = 0.f;
#pragma unroll
        for (int j = 0; j < 4; j++) o[i][j] = 0.f;
    }

    for (int kc = 0; kc < SS; kc += 64) {
        __syncthreads();
        {
            const int c = t >> 2, d0 = (t & 3) * 16;
            const float* kp = Kf + base + (size_t)(kc + c) * DD + d0;
            const float* vp = Vf + base + (size_t)(kc + c) * DD + d0;
#pragma unroll
            for (int i = 0; i < 16; i += 4) {
                float4 kv = *(const float4*)(kp + i);
                Kst[(d0+i+0)*64 + c] = kv.x;
                Kst[(d0+i+1)*64 + c] = kv.y;
                Kst[(d0+i+2)*64 + c] = kv.z;
                Kst[(d0+i+3)*64 + c] = kv.w;
                float4 vv = *(const float4*)(vp + i);
                *(float4*)&Vs[c*64 + d0 + i] = vv;
            }
            if (t < 64) msk[t] = mask[(size_t)b * SS + kc + t];
        }
        __syncthreads();

        float s[4][4];
#pragma unroll
        for (int i = 0; i < 4; i++)
#pragma unroll
            for (int j = 0; j < 4; j++) s[i][j] = 0.f;

        for (int d = 0; d < 64; d++) {
            float a0 = Qs[(ty*4+0)*65 + d];
            float a1 = Qs[(ty*4+1)*65 + d];
            float a2 = Qs[(ty*4+2)*65 + d];
            float a3 = Qs[(ty*4+3)*65 + d];
            float4 bb = *(const float4*)&Kst[d*64 + tx*4];
            s[0][0] = fmaf(a0, bb.x, s[0][0]); s[0][1] = fmaf(a0, bb.y, s[0][1]);
            s[0][2] = fmaf(a0, bb.z, s[0][2]); s[0][3] = fmaf(a0, bb.w, s[0][3]);
            s[1][0] = fmaf(a1, bb.x, s[1][0]); s[1][1] = fmaf(a1, bb.y, s[1][1]);
            s[1][2] = fmaf(a1, bb.z, s[1][2]); s[1][3] = fmaf(a1, bb.w, s[1][3]);
            s[2][0] = fmaf(a2, bb.x, s[2][0]); s[2][1] = fmaf(a2, bb.y, s[2][1]);
            s[2][2] = fmaf(a2, bb.z, s[2][2]); s[2][3] = fmaf(a2, bb.w, s[2][3]);
            s[3][0] = fmaf(a3, bb.x, s[3][0]); s[3][1] = fmaf(a3, bb.y, s[3][1]);
            s[3][2] = fmaf(a3, bb.z, s[3][2]); s[3][3] = fmaf(a3, bb.w, s[3][3]);
        }

#pragma unroll
        for (int j = 0; j < 4; j++)
            if (msk[tx*4 + j] == 0) {
#pragma unroll
                for (int i = 0; i < 4; i++) s[i][j] = -1e9f;
            }

#pragma unroll
        for (int i = 0; i < 4; i++) {
            float mt = fmaxf(fmaxf(s[i][0], s[i][1]), fmaxf(s[i][2], s[i][3]));
#pragma unroll
            for (int off = 1; off < 16; off <<= 1)
                mt = fmaxf(mt, __shfl_xor_sync(0xffffffffu, mt, off));
            float mn = fmaxf(m[i], mt);
            float alpha = __expf(m[i] - mn);
            m[i] = mn;
            float psum = 0.f;
#pragma unroll
            for (int j = 0; j < 4; j++) {
                float p = __expf(s[i][j] - mn);
                s[i][j] = p; psum += p;
            }
#pragma unroll
            for (int off = 1; off < 16; off <<= 1)
                psum += __shfl_xor_sync(0xffffffffu, psum, off);
            l[i] = l[i] * alpha + psum;
#pragma unroll
            for (int j = 0; j < 4; j++) o[i][j] *= alpha;
#pragma unroll
            for (int j = 0; j < 4; j++)
                Ps[(ty*4+i)*65 + tx*4 + j] = s[i][j];
        }
        __syncthreads();

        for (int c = 0; c < 64; c++) {
            float a0 = Ps[(ty*4+0)*65 + c];
            float a1 = Ps[(ty*4+1)*65 + c];
            float a2 = Ps[(ty*4+2)*65 + c];
            float a3 = Ps[(ty*4+3)*65 + c];
            float4 bb = *(const float4*)&Vs[c*64 + tx*4];
            o[0][0] = fmaf(a0, bb.x, o[0][0]); o[0][1] = fmaf(a0, bb.y, o[0][1]);
            o[0][2] = fmaf(a0, bb.z, o[0][2]); o[0][3] = fmaf(a0, bb.w, o[0][3]);
            o[1][0] = fmaf(a1, bb.x, o[1][0]); o[1][1] = fmaf(a1, bb.y, o[1][1]);
            o[1][2] = fmaf(a1, bb.z, o[1][2]); o[1][3] = fmaf(a1, bb.w, o[1][3]);
            o[2][0] = fmaf(a2, bb.x, o[2][0]); o[2][1] = fmaf(a2, bb.y, o[2][1]);
            o[2][2] = fmaf(a2, bb.z, o[2][2]); o[2][3] = fmaf(a2, bb.w, o[2][3]);
            o[3][0] = fmaf(a3, bb.x, o[3][0]); o[3][1] = fmaf(a3, bb.y, o[3][1]);
            o[3][2] = fmaf(a3, bb.z, o[3][2]); o[3][3] = fmaf(a3, bb.w, o[3][3]);
        }
    }

#pragma unroll
    for (int i = 0; i < 4; i++) {
        float inv = 1.0f / l[i];
        float4 r;
        r.x = o[i][0]*inv; r.y = o[i][1]*inv; r.z = o[i][2]*inv; r.w = o[i][3]*inv;
        *(float4*)&ctx[base + (size_t)(qb*64 + ty*4 + i) * DD + tx*4] = r;
    }
}

// ---------------------------------------------------------------------------
// LayerNorm: unbiased std (ddof=1), eps added to std
// ---------------------------------------------------------------------------
__global__ void __launch_bounds__(256)
ln_kernel(const float* __restrict__ in, const float* __restrict__ g,
          const float* __restrict__ be, float* __restrict__ out)
{
    __shared__ float red1[8];
    __shared__ float red2[8];
    const int row = blockIdx.x;
    const int t = threadIdx.x;
    const int warp = t >> 5, lane = t & 31;

    float4 v = *(const float4*)(in + (size_t)row * DD + t*4);

    float s = v.x + v.y + v.z + v.w;
#pragma unroll
    for (int off = 16; off; off >>= 1) s += __shfl_xor_sync(0xffffffffu, s, off);
    if (lane == 0) red1[warp] = s;
    __syncthreads();
    float tot = 0.f;
#pragma unroll
    for (int i = 0; i < 8; i++) tot += red1[i];
    const float mean = tot * (1.0f / DD);

    float dx = v.x - mean, dy = v.y - mean, dz = v.z - mean, dw = v.w - mean;
    float sq = dx*dx + dy*dy + dz*dz + dw*dw;
#pragma unroll
    for (int off = 16; off; off >>= 1) sq += __shfl_xor_sync(0xffffffffu, sq, off);
    if (lane == 0) red2[warp] = sq;
    __syncthreads();
    float sqtot = 0.f;
#pragma unroll
    for (int i = 0; i < 8; i++) sqtot += red2[i];

    const float var = sqtot * (1.0f / (DD - 1));
    const float inv = 1.0f / (sqrtf(var) + 1e-6f);

    float4 gv = *(const float4*)(g  + t*4);
    float4 bv = *(const float4*)(be + t*4);
    float4 r;
    r.x = dx * inv * gv.x + bv.x;
    r.y = dy * inv * gv.y + bv.y;
    r.z = dz * inv * gv.z + bv.z;
    r.w = dw * inv * gv.w + bv.w;
    *(float4*)(out + (size_t)row * DD + t*4) = r;
}

// ---------------------------------------------------------------------------
// kernel_launch
// ---------------------------------------------------------------------------
extern "C" void kernel_launch(void* const* d_in, const int* in_sizes, int n_in,
                              void* d_out, int out_size)
{
    const float* x    = (const float*)d_in[0];
    const int*   mask = (const int*)  d_in[1];
    const float* Wq = (const float*)d_in[2];  const float* bq = (const float*)d_in[3];
    const float* Wk = (const float*)d_in[4];  const float* bk = (const float*)d_in[5];
    const float* Wv = (const float*)d_in[6];  const float* bv = (const float*)d_in[7];
    const float* Wo = (const float*)d_in[8];  const float* bo = (const float*)d_in[9];
    const float* W1 = (const float*)d_in[10]; const float* b1 = (const float*)d_in[11];
    const float* W2 = (const float*)d_in[12]; const float* b2 = (const float*)d_in[13];
    const float* g1 = (const float*)d_in[14]; const float* be1 = (const float*)d_in[15];
    const float* g2 = (const float*)d_in[16]; const float* be2 = (const float*)d_in[17];
    float* out = (float*)d_out;

    float *pq, *pk, *pv, *pctx, *pt0, *px1, *ph;
    cudaGetSymbolAddress((void**)&pq,   g_q);
    cudaGetSymbolAddress((void**)&pk,   g_k);
    cudaGetSymbolAddress((void**)&pv,   g_v);
    cudaGetSymbolAddress((void**)&pctx, g_ctx);
    cudaGetSymbolAddress((void**)&pt0,  g_t0);
    cudaGetSymbolAddress((void**)&px1,  g_x1);
    cudaGetSymbolAddress((void**)&ph,   g_hb);

    const int attn_smem = (64*65 + 64*64 + 64*64 + 64*65) * 4 + 64 * 4;
    cudaFuncSetAttribute(attn_kernel, cudaFuncAttributeMaxDynamicSharedMemorySize,
                         attn_smem);

    dim3 blk(256);
    dim3 gD(DD/128,   ROWS/128);
    dim3 gF(DFFq/128, ROWS/128);

    // QKV projections (tf32 tensor core)
    gemm_tf32<0,0><<<gD, blk>>>(x, Wq, bq, nullptr, pq, ROWS, DD, DD);
    gemm_tf32<0,0><<<gD, blk>>>(x, Wk, bk, nullptr, pk, ROWS, DD, DD);
    gemm_tf32<0,0><<<gD, blk>>>(x, Wv, bv, nullptr, pv, ROWS, DD, DD);

    // attention
    attn_kernel<<<dim3(SS/64, BB*HH), blk, attn_smem>>>(pq, pk, pv, mask, pctx);

    // output projection + residual, then LN1
    gemm_tf32<0,1><<<gD, blk>>>(pctx, Wo, bo, x, pt0, ROWS, DD, DD);
    ln_kernel<<<ROWS, blk>>>(pt0, g1, be1, px1);

    // FFN
    gemm_tf32<1,0><<<gF, blk>>>(px1, W1, b1, nullptr, ph, ROWS, DFFq, DD);
    gemm_tf32<0,1><<<gD, blk>>>(ph, W2, b2, px1, pt0, ROWS, DD, DFFq);

    // LN2 -> output
    ln_kernel<<<ROWS, blk>>>(pt0, g2, be2, out);
}

// round 7
// speedup vs baseline: 3.3507x; 1.6879x over previous
#include <cuda_runtime.h>
#include <math.h>

// Problem constants
#define BB   4
#define SS   2048
#define DD   1024
#define HH   16
#define DKK  64
#define DFFq 4096
#define ROWS (BB*SS)          // 8192

// ---------------------------------------------------------------------------
// Scratch (device globals; no allocation allowed)
// ---------------------------------------------------------------------------
__device__ float g_q  [ (size_t)ROWS*DD ];
__device__ float g_k  [ (size_t)ROWS*DD ];
__device__ float g_v  [ (size_t)ROWS*DD ];
__device__ float g_ctx[ (size_t)ROWS*DD ];
__device__ float g_t0 [ (size_t)ROWS*DD ];
__device__ float g_x1 [ (size_t)ROWS*DD ];
__device__ float g_hb [ (size_t)ROWS*DFFq ];

// ---------------------------------------------------------------------------
// tf32 helpers
// ---------------------------------------------------------------------------
__device__ __forceinline__ unsigned cvt_tf32(float x) {
    unsigned r;
    asm("cvt.rna.tf32.f32 %0, %1;" : "=r"(r) : "f"(x));
    return r;
}

__device__ __forceinline__ void mma_tf32(float* c, const unsigned* a, const unsigned* b) {
    asm volatile(
        "mma.sync.aligned.m16n8k8.row.col.f32.tf32.tf32.f32 "
        "{%0,%1,%2,%3}, {%4,%5,%6,%7}, {%8,%9}, {%0,%1,%2,%3};"
        : "+f"(c[0]), "+f"(c[1]), "+f"(c[2]), "+f"(c[3])
        : "r"(a[0]), "r"(a[1]), "r"(a[2]), "r"(a[3]),
          "r"(b[0]), "r"(b[1]));
}

// ---------------------------------------------------------------------------
// GEMM (tensor-core tf32): C[M,N] = A[M,K] * Bw[N,K]^T + bias (+Res)(+relu)
// ---------------------------------------------------------------------------
#define SPAD 36

template<int RELU, int RES>
__global__ void __launch_bounds__(256, 2)
gemm_tf32(const float* __restrict__ A, const float* __restrict__ Bw,
          const float* __restrict__ bias, const float* __restrict__ Res,
          float* __restrict__ C, int M, int N, int K)
{
    __shared__ __align__(16) unsigned As[128 * SPAD];
    __shared__ __align__(16) unsigned Bs[128 * SPAD];

    const int t = threadIdx.x;
    const int w = t >> 5, lane = t & 31;
    const int gid = lane >> 2, qid = lane & 3;
    const int bm = blockIdx.y, bn = blockIdx.x;
    const int wm = (w >> 2) * 64;
    const int wn = (w & 3) * 32;

    const int r0 = t >> 3;
    const int qc = t & 7;

    const float* Ap = A  + (size_t)(bm*128 + r0) * K + qc*4;
    const float* Bp = Bw + (size_t)(bn*128 + r0) * K + qc*4;

    float pa[16], pb[16];
#pragma unroll
    for (int i = 0; i < 4; i++) {
        float4 va = *(const float4*)(Ap + (size_t)(32*i) * K);
        float4 vb = *(const float4*)(Bp + (size_t)(32*i) * K);
        pa[i*4+0]=va.x; pa[i*4+1]=va.y; pa[i*4+2]=va.z; pa[i*4+3]=va.w;
        pb[i*4+0]=vb.x; pb[i*4+1]=vb.y; pb[i*4+2]=vb.z; pb[i*4+3]=vb.w;
    }

    float acc[4][4][4];
#pragma unroll
    for (int i = 0; i < 4; i++)
#pragma unroll
        for (int j = 0; j < 4; j++)
#pragma unroll
            for (int c = 0; c < 4; c++) acc[i][j][c] = 0.f;

    for (int k0 = 0; k0 < K; k0 += 32) {
        __syncthreads();
#pragma unroll
        for (int i = 0; i < 4; i++) {
            uint4 sa, sb;
            sa.x = cvt_tf32(pa[i*4+0]); sa.y = cvt_tf32(pa[i*4+1]);
            sa.z = cvt_tf32(pa[i*4+2]); sa.w = cvt_tf32(pa[i*4+3]);
            sb.x = cvt_tf32(pb[i*4+0]); sb.y = cvt_tf32(pb[i*4+1]);
            sb.z = cvt_tf32(pb[i*4+2]); sb.w = cvt_tf32(pb[i*4+3]);
            *(uint4*)&As[(r0 + 32*i) * SPAD + qc*4] = sa;
            *(uint4*)&Bs[(r0 + 32*i) * SPAD + qc*4] = sb;
        }
        __syncthreads();

        if (k0 + 32 < K) {
#pragma unroll
            for (int i = 0; i < 4; i++) {
                float4 va = *(const float4*)(Ap + (size_t)(32*i) * K + (k0 + 32));
                float4 vb = *(const float4*)(Bp + (size_t)(32*i) * K + (k0 + 32));
                pa[i*4+0]=va.x; pa[i*4+1]=va.y; pa[i*4+2]=va.z; pa[i*4+3]=va.w;
                pb[i*4+0]=vb.x; pb[i*4+1]=vb.y; pb[i*4+2]=vb.z; pb[i*4+3]=vb.w;
            }
        }

#pragma unroll
        for (int ks = 0; ks < 4; ks++) {
            const int kk = ks * 8;
            unsigned afr[4][4], bfr[4][2];
#pragma unroll
            for (int i = 0; i < 4; i++) {
                const int r = wm + i*16 + gid;
                afr[i][0] = As[r       * SPAD + kk + qid];
                afr[i][1] = As[(r + 8) * SPAD + kk + qid];
                afr[i][2] = As[r       * SPAD + kk + qid + 4];
                afr[i][3] = As[(r + 8) * SPAD + kk + qid + 4];
            }
#pragma unroll
            for (int j = 0; j < 4; j++) {
                const int n = wn + j*8 + gid;
                bfr[j][0] = Bs[n * SPAD + kk + qid];
                bfr[j][1] = Bs[n * SPAD + kk + qid + 4];
            }
#pragma unroll
            for (int i = 0; i < 4; i++)
#pragma unroll
                for (int j = 0; j < 4; j++)
                    mma_tf32(acc[i][j], afr[i], bfr[j]);
        }
    }

#pragma unroll
    for (int i = 0; i < 4; i++) {
#pragma unroll
        for (int j = 0; j < 4; j++) {
            const int row = bm*128 + wm + i*16 + gid;
            const int col = bn*128 + wn + j*8 + 2*qid;
            float2 bi = *(const float2*)&bias[col];
            float2 r0v, r1v;
            r0v.x = acc[i][j][0] + bi.x;  r0v.y = acc[i][j][1] + bi.y;
            r1v.x = acc[i][j][2] + bi.x;  r1v.y = acc[i][j][3] + bi.y;
            if (RES) {
                float2 a0 = *(const float2*)&Res[(size_t)row*N + col];
                float2 a1 = *(const float2*)&Res[(size_t)(row+8)*N + col];
                r0v.x += a0.x; r0v.y += a0.y;
                r1v.x += a1.x; r1v.y += a1.y;
            }
            if (RELU) {
                r0v.x = fmaxf(r0v.x, 0.f); r0v.y = fmaxf(r0v.y, 0.f);
                r1v.x = fmaxf(r1v.x, 0.f); r1v.y = fmaxf(r1v.y, 0.f);
            }
            *(float2*)&C[(size_t)row    *N + col] = r0v;
            *(float2*)&C[(size_t)(row+8)*N + col] = r1v;
        }
    }
}

// ---------------------------------------------------------------------------
// Flash attention v2 (tensor core tf32):
// CTA = 128 queries x one head. 8 warps x 16 query rows. 64-key tiles.
// S = Q K^T via m16n8k8 (A: Qs rows, B: Ks rows [c][d]); online softmax on
// fragments; P -> smem (warp-local rows, tf32); O += P V via m16n8k8
// (B: Vt rows [d][c]). Pad 68 (mod 32 == 4) -> fragment LDS conflict-free.
// ---------------------------------------------------------------------------
#define APAD 68

__global__ void __launch_bounds__(256, 1)
attn_tc(const float* __restrict__ Q, const float* __restrict__ Kf,
        const float* __restrict__ Vf, const int* __restrict__ mask,
        float* __restrict__ ctx)
{
    extern __shared__ unsigned smu[];
    unsigned* Qs = smu;                    // [128][APAD]
    unsigned* Ks = Qs + 128*APAD;          // [64][APAD]   K[c][d]
    unsigned* Vt = Ks + 64*APAD;           // [64][APAD]   V^T[d][c]
    unsigned* Ps = Vt + 64*APAD;           // [128][APAD]
    int*     msk = (int*)(Ps + 128*APAD);  // [64]

    const int t = threadIdx.x, w = t >> 5, lane = t & 31;
    const int gid = lane >> 2, qid = lane & 3;
    const int qb = blockIdx.x, bh = blockIdx.y;
    const int b = bh / HH, h = bh % HH;
    const int wm = w * 16;

    const size_t base = (size_t)b * SS * DD + (size_t)h * DKK;

    // --- load Q tile (128x64), prescaled by 1/8, tf32. Warp-local rows. ---
    {
        const int r = t >> 1, c0 = (t & 1) * 32;
        const float* qp = Q + base + (size_t)(qb*128 + r) * DD + c0;
#pragma unroll
        for (int i = 0; i < 32; i += 4) {
            float4 v = *(const float4*)(qp + i);
            uint4 s;
            s.x = cvt_tf32(v.x * 0.125f); s.y = cvt_tf32(v.y * 0.125f);
            s.z = cvt_tf32(v.z * 0.125f); s.w = cvt_tf32(v.w * 0.125f);
            *(uint4*)&Qs[r*APAD + c0 + i] = s;
        }
    }

    float m0 = -1e30f, m1 = -1e30f, l0 = 0.f, l1 = 0.f;
    float o[8][4];
#pragma unroll
    for (int j = 0; j < 8; j++)
#pragma unroll
        for (int c = 0; c < 4; c++) o[j][c] = 0.f;

    for (int kc = 0; kc < SS; kc += 64) {
        __syncthreads();   // prior iteration's mma reads of Ks/Vt done
        {
            const int r = t >> 2, c0 = (t & 3) * 16;
            const float* kp = Kf + base + (size_t)(kc + r) * DD + c0;
            const float* vp = Vf + base + (size_t)(kc + r) * DD + c0;
#pragma unroll
            for (int i = 0; i < 16; i += 4) {
                float4 kv = *(const float4*)(kp + i);
                uint4 s;
                s.x = cvt_tf32(kv.x); s.y = cvt_tf32(kv.y);
                s.z = cvt_tf32(kv.z); s.w = cvt_tf32(kv.w);
                *(uint4*)&Ks[r*APAD + c0 + i] = s;
                float4 vv = *(const float4*)(vp + i);
                Vt[(c0+i+0)*APAD + r] = cvt_tf32(vv.x);
                Vt[(c0+i+1)*APAD + r] = cvt_tf32(vv.y);
                Vt[(c0+i+2)*APAD + r] = cvt_tf32(vv.z);
                Vt[(c0+i+3)*APAD + r] = cvt_tf32(vv.w);
            }
            if (t < 64) msk[t] = mask[(size_t)b * SS + kc + t];
        }
        __syncthreads();

        // --- S = Q K^T (warp rows wm..wm+15, cols 0..63) ---
        float sacc[8][4];
#pragma unroll
        for (int j = 0; j < 8; j++)
#pragma unroll
            for (int c = 0; c < 4; c++) sacc[j][c] = 0.f;

#pragma unroll
        for (int kk = 0; kk < 64; kk += 8) {
            unsigned a[4];
            a[0] = Qs[(wm+gid)  *APAD + kk + qid];
            a[1] = Qs[(wm+gid+8)*APAD + kk + qid];
            a[2] = Qs[(wm+gid)  *APAD + kk + qid + 4];
            a[3] = Qs[(wm+gid+8)*APAD + kk + qid + 4];
#pragma unroll
            for (int j = 0; j < 8; j++) {
                unsigned bf[2];
                bf[0] = Ks[(8*j+gid)*APAD + kk + qid];
                bf[1] = Ks[(8*j+gid)*APAD + kk + qid + 4];
                mma_tf32(sacc[j], a, bf);
            }
        }

        // --- mask ---
#pragma unroll
        for (int j = 0; j < 8; j++) {
            const int c = 8*j + 2*qid;
            if (msk[c]   == 0) { sacc[j][0] = -1e9f; sacc[j][2] = -1e9f; }
            if (msk[c+1] == 0) { sacc[j][1] = -1e9f; sacc[j][3] = -1e9f; }
        }

        // --- online softmax (rows gid, gid+8) ---
        float mt0 = -1e30f, mt1 = -1e30f;
#pragma unroll
        for (int j = 0; j < 8; j++) {
            mt0 = fmaxf(mt0, fmaxf(sacc[j][0], sacc[j][1]));
            mt1 = fmaxf(mt1, fmaxf(sacc[j][2], sacc[j][3]));
        }
        mt0 = fmaxf(mt0, __shfl_xor_sync(0xffffffffu, mt0, 1));
        mt0 = fmaxf(mt0, __shfl_xor_sync(0xffffffffu, mt0, 2));
        mt1 = fmaxf(mt1, __shfl_xor_sync(0xffffffffu, mt1, 1));
        mt1 = fmaxf(mt1, __shfl_xor_sync(0xffffffffu, mt1, 2));

        const float mn0 = fmaxf(m0, mt0), mn1 = fmaxf(m1, mt1);
        const float al0 = __expf(m0 - mn0), al1 = __expf(m1 - mn1);
        m0 = mn0; m1 = mn1;

        float ps0 = 0.f, ps1 = 0.f;
#pragma unroll
        for (int j = 0; j < 8; j++) {
            float p00 = __expf(sacc[j][0] - mn0);
            float p01 = __expf(sacc[j][1] - mn0);
            float p10 = __expf(sacc[j][2] - mn1);
            float p11 = __expf(sacc[j][3] - mn1);
            ps0 += p00 + p01;  ps1 += p10 + p11;
            uint2 w0, w1;
            w0.x = cvt_tf32(p00); w0.y = cvt_tf32(p01);
            w1.x = cvt_tf32(p10); w1.y = cvt_tf32(p11);
            *(uint2*)&Ps[(wm+gid)  *APAD + 8*j + 2*qid] = w0;
            *(uint2*)&Ps[(wm+gid+8)*APAD + 8*j + 2*qid] = w1;
        }
        ps0 += __shfl_xor_sync(0xffffffffu, ps0, 1);
        ps0 += __shfl_xor_sync(0xffffffffu, ps0, 2);
        ps1 += __shfl_xor_sync(0xffffffffu, ps1, 1);
        ps1 += __shfl_xor_sync(0xffffffffu, ps1, 2);
        l0 = l0 * al0 + ps0;
        l1 = l1 * al1 + ps1;

#pragma unroll
        for (int j = 0; j < 8; j++) {
            o[j][0] *= al0; o[j][1] *= al0;
            o[j][2] *= al1; o[j][3] *= al1;
        }
        __syncwarp();   // Ps rows are warp-local; make writes visible in-warp

        // --- O += P V  (A: Ps rows, B: Vt[d][c]) ---
#pragma unroll
        for (int kk = 0; kk < 64; kk += 8) {
            unsigned a[4];
            a[0] = Ps[(wm+gid)  *APAD + kk + qid];
            a[1] = Ps[(wm+gid+8)*APAD + kk + qid];
            a[2] = Ps[(wm+gid)  *APAD + kk + qid + 4];
            a[3] = Ps[(wm+gid+8)*APAD + kk + qid + 4];
#pragma unroll
            for (int j = 0; j < 8; j++) {
                unsigned bf[2];
                bf[0] = Vt[(8*j+gid)*APAD + kk + qid];
                bf[1] = Vt[(8*j+gid)*APAD + kk + qid + 4];
                mma_tf32(o[j], a, bf);
            }
        }
    }

    // --- epilogue: normalize and store ---
    const float inv0 = 1.0f / l0, inv1 = 1.0f / l1;
    const int row = qb*128 + wm + gid;
#pragma unroll
    for (int j = 0; j < 8; j++) {
        const int col = 8*j + 2*qid;
        float2 r0v, r1v;
        r0v.x = o[j][0]*inv0; r0v.y = o[j][1]*inv0;
        r1v.x = o[j][2]*inv1; r1v.y = o[j][3]*inv1;
        *(float2*)&ctx[base + (size_t)row    *DD + col] = r0v;
        *(float2*)&ctx[base + (size_t)(row+8)*DD + col] = r1v;
    }
}

// ---------------------------------------------------------------------------
// LayerNorm: unbiased std (ddof=1), eps added to std
// ---------------------------------------------------------------------------
__global__ void __launch_bounds__(256)
ln_kernel(const float* __restrict__ in, const float* __restrict__ g,
          const float* __restrict__ be, float* __restrict__ out)
{
    __shared__ float red1[8];
    __shared__ float red2[8];
    const int row = blockIdx.x;
    const int t = threadIdx.x;
    const int warp = t >> 5, lane = t & 31;

    float4 v = *(const float4*)(in + (size_t)row * DD + t*4);

    float s = v.x + v.y + v.z + v.w;
#pragma unroll
    for (int off = 16; off; off >>= 1) s += __shfl_xor_sync(0xffffffffu, s, off);
    if (lane == 0) red1[warp] = s;
    __syncthreads();
    float tot = 0.f;
#pragma unroll
    for (int i = 0; i < 8; i++) tot += red1[i];
    const float mean = tot * (1.0f / DD);

    float dx = v.x - mean, dy = v.y - mean, dz = v.z - mean, dw = v.w - mean;
    float sq = dx*dx + dy*dy + dz*dz + dw*dw;
#pragma unroll
    for (int off = 16; off; off >>= 1) sq += __shfl_xor_sync(0xffffffffu, sq, off);
    if (lane == 0) red2[warp] = sq;
    __syncthreads();
    float sqtot = 0.f;
#pragma unroll
    for (int i = 0; i < 8; i++) sqtot += red2[i];

    const float var = sqtot * (1.0f / (DD - 1));
    const float inv = 1.0f / (sqrtf(var) + 1e-6f);

    float4 gv = *(const float4*)(g  + t*4);
    float4 bv = *(const float4*)(be + t*4);
    float4 r;
    r.x = dx * inv * gv.x + bv.x;
    r.y = dy * inv * gv.y + bv.y;
    r.z = dz * inv * gv.z + bv.z;
    r.w = dw * inv * gv.w + bv.w;
    *(float4*)(out + (size_t)row * DD + t*4) = r;
}

// ---------------------------------------------------------------------------
// kernel_launch
// ---------------------------------------------------------------------------
extern "C" void kernel_launch(void* const* d_in, const int* in_sizes, int n_in,
                              void* d_out, int out_size)
{
    const float* x    = (const float*)d_in[0];
    const int*   mask = (const int*)  d_in[1];
    const float* Wq = (const float*)d_in[2];  const float* bq = (const float*)d_in[3];
    const float* Wk = (const float*)d_in[4];  const float* bk = (const float*)d_in[5];
    const float* Wv = (const float*)d_in[6];  const float* bv = (const float*)d_in[7];
    const float* Wo = (const float*)d_in[8];  const float* bo = (const float*)d_in[9];
    const float* W1 = (const float*)d_in[10]; const float* b1 = (const float*)d_in[11];
    const float* W2 = (const float*)d_in[12]; const float* b2 = (const float*)d_in[13];
    const float* g1 = (const float*)d_in[14]; const float* be1 = (const float*)d_in[15];
    const float* g2 = (const float*)d_in[16]; const float* be2 = (const float*)d_in[17];
    float* out = (float*)d_out;

    float *pq, *pk, *pv, *pctx, *pt0, *px1, *ph;
    cudaGetSymbolAddress((void**)&pq,   g_q);
    cudaGetSymbolAddress((void**)&pk,   g_k);
    cudaGetSymbolAddress((void**)&pv,   g_v);
    cudaGetSymbolAddress((void**)&pctx, g_ctx);
    cudaGetSymbolAddress((void**)&pt0,  g_t0);
    cudaGetSymbolAddress((void**)&px1,  g_x1);
    cudaGetSymbolAddress((void**)&ph,   g_hb);

    const int attn_smem = (128*APAD + 64*APAD + 64*APAD + 128*APAD) * 4 + 64*4;
    cudaFuncSetAttribute(attn_tc, cudaFuncAttributeMaxDynamicSharedMemorySize,
                         attn_smem);

    dim3 blk(256);
    dim3 gD(DD/128,   ROWS/128);
    dim3 gF(DFFq/128, ROWS/128);

    // QKV projections (tf32 tensor core)
    gemm_tf32<0,0><<<gD, blk>>>(x, Wq, bq, nullptr, pq, ROWS, DD, DD);
    gemm_tf32<0,0><<<gD, blk>>>(x, Wk, bk, nullptr, pk, ROWS, DD, DD);
    gemm_tf32<0,0><<<gD, blk>>>(x, Wv, bv, nullptr, pv, ROWS, DD, DD);

    // attention (tensor core)
    attn_tc<<<dim3(SS/128, BB*HH), blk, attn_smem>>>(pq, pk, pv, mask, pctx);

    // output projection + residual, then LN1
    gemm_tf32<0,1><<<gD, blk>>>(pctx, Wo, bo, x, pt0, ROWS, DD, DD);
    ln_kernel<<<ROWS, blk>>>(pt0, g1, be1, px1);

    // FFN
    gemm_tf32<1,0><<<gF, blk>>>(px1, W1, b1, nullptr, ph, ROWS, DFFq, DD);
    gemm_tf32<0,1><<<gD, blk>>>(ph, W2, b2, px1, pt0, ROWS, DD, DFFq);

    // LN2 -> output
    ln_kernel<<<ROWS, blk>>>(pt0, g2, be2, out);
}